// round 1
// baseline (speedup 1.0000x reference)
#include <cuda_runtime.h>
#include <math.h>

#define NN      50000
#define DEG     32
#define NODE    128
#define TOW     4
#define IN_T    32
#define OUT_T   32
#define KEFF    160          // folded posttrans inner dim: 32 (ht) + 128 (agg)
#define MB      16           // nodes per block in main kernel (50000 % 16 == 0 -> 3125 blocks)

// Scratch (device-global: no runtime allocation allowed)
__device__ float g_u[NN * NODE];              // 25.6 MB: ht @ W_pre[:32]
__device__ float g_v[NN * NODE];              // 25.6 MB: ht @ W_pre[32:] + b_pre
__device__ float g_Weff[TOW * KEFF * OUT_T];  // 80 KB folded posttrans weights

// ---------------------------------------------------------------------------
// Kernel 0: fold scaler multipliers into W_post.
// z = [ht(32), agg(128), sc*agg(128), agg/sc(128)]  ->  z_eff = [ht(32), agg(128)]
// W_eff[k<32] = W_post[k];  W_eff[32+ka] = W[32+ka] + sc*W[160+ka] + (1/sc)*W[288+ka]
// ---------------------------------------------------------------------------
__global__ void k_fold(const float* __restrict__ W_post) {
    int i = blockIdx.x * 256 + threadIdx.x;       // over TOW*KEFF*OUT_T = 20480
    if (i >= TOW * KEFF * OUT_T) return;
    int o = i & 31;
    int k = (i >> 5) % KEFF;
    int t = i / (KEFF * OUT_T);
    const float sc  = logf((float)(DEG + 1)) / logf(5.0f);   // deg == 32 for every node
    const float isc = 1.0f / sc;
    const float* Wt = W_post + t * 416 * OUT_T;
    float w;
    if (k < 32) {
        w = Wt[k * OUT_T + o];
    } else {
        int ka = k - 32;
        w = Wt[(32 + ka) * OUT_T + o]
          + sc  * Wt[(160 + ka) * OUT_T + o]
          + isc * Wt[(288 + ka) * OUT_T + o];
    }
    g_Weff[i] = w;
}

// ---------------------------------------------------------------------------
// Kernel 1: per-node pretrans halves.
// u[n,t*32+o] = sum_k ht[n,t*32+k] * W_pre[t,k,o]
// v[n,t*32+o] = sum_k ht[n,t*32+k] * W_pre[t,32+k,o] + b_pre[t,o]
// 32 nodes / block, 128 threads (one per output feature).
// ---------------------------------------------------------------------------
__global__ void __launch_bounds__(128) k_uv(const float* __restrict__ h,
                                            const float* __restrict__ W_pre,
                                            const float* __restrict__ b_pre) {
    __shared__ __align__(16) float Wp[TOW * 64 * OUT_T];   // 32 KB
    __shared__ __align__(16) float hts[32 * NODE];          // 16 KB
    int tid  = threadIdx.x;
    int base = blockIdx.x * 32;

    for (int i = tid; i < TOW * 64 * OUT_T; i += 128) Wp[i] = W_pre[i];
    for (int i = tid; i < 32 * NODE; i += 128) {
        int n = base + (i >> 7);
        hts[i] = (n < NN) ? h[n * NODE + (i & 127)] : 0.0f;
    }
    __syncthreads();

    int t = tid >> 5, o = tid & 31;
    float bp = b_pre[t * OUT_T + o];
    const float* wt = &Wp[t * 64 * OUT_T + o];

    for (int m = 0; m < 32; m++) {
        int n = base + m;
        if (n >= NN) break;
        const float* hrow = &hts[m * NODE + t * IN_T];
        float au = 0.0f, av = 0.0f;
#pragma unroll
        for (int k = 0; k < IN_T; k++) {
            float hv = hrow[k];
            au += hv * wt[k * OUT_T];
            av += hv * wt[(32 + k) * OUT_T];
        }
        g_u[n * NODE + tid] = au;
        g_v[n * NODE + tid] = av + bp;
    }
}

// ---------------------------------------------------------------------------
// Kernel 2: gather+aggregate -> posttrans (folded) -> mix -> residual.
// 16 nodes / block, 256 threads. Feature-parallel aggregation (coalesced 512B
// gathers of u[src]); register-blocked GEMMs with smem LDS.128 broadcasts.
// ---------------------------------------------------------------------------
__global__ void __launch_bounds__(256) k_main(const float* __restrict__ h,
                                              const int*   __restrict__ src,
                                              const float* __restrict__ b_post,
                                              const float* __restrict__ W_mix,
                                              const float* __restrict__ b_mix,
                                              float*       __restrict__ out) {
    __shared__ __align__(16) float z_s[MB * TOW * KEFF];   // 16*640 f = 40 KB
    __shared__ __align__(16) float hp_s[MB * NODE];        //  8 KB

    int tid  = threadIdx.x;
    int half = tid >> 7;          // 0/1 : which node of each pair
    int jj   = tid & 127;         // feature index
    int t    = jj >> 5, o = jj & 31;
    int base = blockIdx.x * MB;

    // ---- Phase A: gather u[src], e = relu(u+v), running mean/max/min/meansq
    for (int mp = 0; mp < MB / 2; mp++) {
        int m = mp * 2 + half;
        int n = base + m;
        float vj = g_v[n * NODE + jj];
        const int4* sp4 = (const int4*)(src + n * DEG);
        int4 s[DEG / 4];
#pragma unroll
        for (int i = 0; i < DEG / 4; i++) s[i] = sp4[i];   // uniform per half-block

        float sum = 0.0f, sq = 0.0f, mx = -3.4e38f, mn = 3.4e38f;
#pragma unroll
        for (int i = 0; i < DEG / 4; i++) {
            int4 si = s[i];
#define PROC(SS) { float e = fmaxf(g_u[(SS) * NODE + jj] + vj, 0.0f); \
                   sum += e; sq += e * e; mx = fmaxf(mx, e); mn = fminf(mn, e); }
            PROC(si.x); PROC(si.y); PROC(si.z); PROC(si.w);
#undef PROC
        }
        float mean = sum * (1.0f / DEG);
        float sd   = sqrtf(fmaxf(sq * (1.0f / DEG) - mean * mean, 0.0f) + 1e-5f);

        float* zr = &z_s[m * (TOW * KEFF) + t * KEFF];
        zr[o]       = h[n * NODE + jj];   // ht slice
        zr[32 + o]  = mean;
        zr[64 + o]  = mx;
        zr[96 + o]  = mn;
        zr[128 + o] = sd;
    }
    __syncthreads();

    // ---- Phase B: posttrans hp = relu(z_eff @ W_eff + b_post)
    float acc[MB / 2];
    {
        float bp = b_post[t * OUT_T + o];
#pragma unroll
        for (int mp = 0; mp < MB / 2; mp++) acc[mp] = bp;
        const float* W = &g_Weff[t * KEFF * OUT_T + o];
        for (int k = 0; k < KEFF; k += 4) {
            float w0 = W[(k + 0) * OUT_T];
            float w1 = W[(k + 1) * OUT_T];
            float w2 = W[(k + 2) * OUT_T];
            float w3 = W[(k + 3) * OUT_T];
#pragma unroll
            for (int mp = 0; mp < MB / 2; mp++) {
                int m = mp * 2 + half;
                float4 zv = *(const float4*)&z_s[m * (TOW * KEFF) + t * KEFF + k];
                acc[mp] += zv.x * w0 + zv.y * w1 + zv.z * w2 + zv.w * w3;
            }
        }
#pragma unroll
        for (int mp = 0; mp < MB / 2; mp++) {
            int m = mp * 2 + half;
            hp_s[m * NODE + jj] = fmaxf(acc[mp], 0.0f);
        }
    }
    __syncthreads();

    // ---- Phase C: mix (leaky_relu(hp @ W_mix + b_mix)) + residual
    {
        float bm = b_mix[jj];
#pragma unroll
        for (int mp = 0; mp < MB / 2; mp++) acc[mp] = bm;
        const float* Wm = W_mix + jj;
        for (int k = 0; k < NODE; k += 4) {
            float w0 = Wm[(k + 0) * NODE];
            float w1 = Wm[(k + 1) * NODE];
            float w2 = Wm[(k + 2) * NODE];
            float w3 = Wm[(k + 3) * NODE];
#pragma unroll
            for (int mp = 0; mp < MB / 2; mp++) {
                int m = mp * 2 + half;
                float4 hv = *(const float4*)&hp_s[m * NODE + k];
                acc[mp] += hv.x * w0 + hv.y * w1 + hv.z * w2 + hv.w * w3;
            }
        }
#pragma unroll
        for (int mp = 0; mp < MB / 2; mp++) {
            int m = mp * 2 + half;
            int n = base + m;
            float x  = acc[mp];
            float lo = (x >= 0.0f) ? x : 0.01f * x;
            out[n * NODE + jj] = h[n * NODE + jj] + lo;
        }
    }
}

// ---------------------------------------------------------------------------
extern "C" void kernel_launch(void* const* d_in, const int* in_sizes, int n_in,
                              void* d_out, int out_size) {
    const float* h      = (const float*)d_in[0];
    const int*   src    = (const int*)  d_in[1];
    // d_in[2] = dst (structurally repeat(arange(N), 32) -> implicit, unused)
    const float* W_pre  = (const float*)d_in[3];
    const float* b_pre  = (const float*)d_in[4];
    const float* W_post = (const float*)d_in[5];
    const float* b_post = (const float*)d_in[6];
    const float* W_mix  = (const float*)d_in[7];
    const float* b_mix  = (const float*)d_in[8];
    float* out = (float*)d_out;

    k_fold<<<(TOW * KEFF * OUT_T + 255) / 256, 256>>>(W_post);
    k_uv  <<<(NN + 31) / 32, 128>>>(h, W_pre, b_pre);
    k_main<<<NN / MB, 256>>>(h, src, b_post, W_mix, b_mix, out);
}

// round 3
// speedup vs baseline: 1.0343x; 1.0343x over previous
#include <cuda_runtime.h>
#include <math.h>

#define NN      50000
#define DEG     32
#define NODE    128
#define TOW     4
#define IN_T    32
#define OUT_T   32
#define KEFF    160          // folded posttrans inner dim: 32 (ht) + 128 (agg)
#define MB      16           // nodes per block in main kernel

typedef unsigned long long u64;

// Scratch (device-global: no runtime allocation allowed)
__device__ float g_u[NN * NODE];                 // 25.6 MB
__device__ float g_v[NN * NODE];                 // 25.6 MB
__device__ float g_WeffT[TOW * KEFF * OUT_T];    // folded posttrans, layout [t][k/4][o][4]
__device__ float g_WmixT[NODE * NODE];           // W_mix, layout [k/4][j][4]

// ---- packed f32x2 helpers -------------------------------------------------
#define FMA2(d, a, b, c) asm("fma.rn.f32x2 %0, %1, %2, %3;" : "=l"(d) : "l"(a), "l"(b), "l"(c))
#define PACK2(out, lo, hi) asm("mov.b64 %0, {%1, %2};" : "=l"(out) : "f"(lo), "f"(hi))
__device__ __forceinline__ float hsum2(u64 v) {
    unsigned int lo, hi;
    asm("mov.b64 {%0, %1}, %2;" : "=r"(lo), "=r"(hi) : "l"(v));
    return __uint_as_float(lo) + __uint_as_float(hi);
}

// ---------------------------------------------------------------------------
// Kernel 0: fold scalers into W_post -> g_WeffT (transposed for LDG.128 per
// lane), and transpose W_mix -> g_WmixT.
// ---------------------------------------------------------------------------
__global__ void k_fold(const float* __restrict__ W_post,
                       const float* __restrict__ W_mix) {
    int i = blockIdx.x * 256 + threadIdx.x;
    const int NW = TOW * KEFF * OUT_T;          // 20480
    if (i < NW) {
        int o = i & 31;
        int k = (i >> 5) % KEFF;
        int t = i / (KEFF * OUT_T);
        const float sc  = logf((float)(DEG + 1)) / logf(5.0f);
        const float isc = 1.0f / sc;
        const float* Wt = W_post + t * 416 * OUT_T;
        float w;
        if (k < 32) {
            w = Wt[k * OUT_T + o];
        } else {
            int ka = k - 32;
            w = Wt[(32 + ka) * OUT_T + o]
              + sc  * Wt[(160 + ka) * OUT_T + o]
              + isc * Wt[(288 + ka) * OUT_T + o];
        }
        // layout: [t][k/4][o][k%4]
        g_WeffT[t * KEFF * OUT_T + (k >> 2) * (OUT_T * 4) + o * 4 + (k & 3)] = w;
    } else if (i < NW + NODE * NODE) {
        int j = i - NW;
        int k = j >> 7, col = j & 127;
        g_WmixT[(k >> 2) * (NODE * 4) + col * 4 + (k & 3)] = W_mix[k * NODE + col];
    }
}

// ---------------------------------------------------------------------------
// Kernel 1: per-node pretrans halves (u = ht@Wpre[:32], v = ht@Wpre[32:]+b).
// ---------------------------------------------------------------------------
__global__ void __launch_bounds__(128) k_uv(const float* __restrict__ h,
                                            const float* __restrict__ W_pre,
                                            const float* __restrict__ b_pre) {
    __shared__ __align__(16) float Wp[TOW * 64 * OUT_T];
    __shared__ __align__(16) float hts[32 * NODE];
    int tid  = threadIdx.x;
    int base = blockIdx.x * 32;

    for (int i = tid; i < TOW * 64 * OUT_T; i += 128) Wp[i] = W_pre[i];
    for (int i = tid; i < 32 * NODE; i += 128) {
        int n = base + (i >> 7);
        hts[i] = (n < NN) ? h[n * NODE + (i & 127)] : 0.0f;
    }
    __syncthreads();

    int t = tid >> 5, o = tid & 31;
    float bp = b_pre[t * OUT_T + o];
    const float* wt = &Wp[t * 64 * OUT_T + o];

    for (int m = 0; m < 32; m++) {
        int n = base + m;
        if (n >= NN) break;
        const float* hrow = &hts[m * NODE + t * IN_T];
        float au = 0.0f, av = 0.0f;
#pragma unroll
        for (int k = 0; k < IN_T; k++) {
            float hv = hrow[k];
            au += hv * wt[k * OUT_T];
            av += hv * wt[(32 + k) * OUT_T];
        }
        g_u[n * NODE + tid] = au;
        g_v[n * NODE + tid] = av + bp;
    }
}

// ---------------------------------------------------------------------------
// Kernel 2: gather+aggregate -> posttrans (f32x2 packed) -> mix -> residual.
// ---------------------------------------------------------------------------
__global__ void __launch_bounds__(256) k_main(const float* __restrict__ h,
                                              const int*   __restrict__ src,
                                              const float* __restrict__ b_post,
                                              const float* __restrict__ b_mix,
                                              float*       __restrict__ out) {
    __shared__ __align__(16) float z_s[MB * TOW * KEFF];   // 40 KB
    __shared__ __align__(16) float hp_s[MB * NODE];        //  8 KB

    int tid  = threadIdx.x;
    int half = tid >> 7;
    int jj   = tid & 127;
    int t    = jj >> 5, o = jj & 31;
    int base = blockIdx.x * MB;

    // ---- Phase A: gather u[src], e = relu(u+v), mean/max/min/std
    for (int mp = 0; mp < MB / 2; mp++) {
        int m = mp * 2 + half;
        int n = base + m;
        float vj = g_v[n * NODE + jj];
        const int4* sp4 = (const int4*)(src + n * DEG);
        int4 s[DEG / 4];
#pragma unroll
        for (int i = 0; i < DEG / 4; i++) s[i] = sp4[i];

        float sum = 0.0f, sq = 0.0f, mx = -3.4e38f, mn = 3.4e38f;
#pragma unroll
        for (int i = 0; i < DEG / 4; i++) {
            int4 si = s[i];
#define PROC(SS) { float e = fmaxf(g_u[(SS) * NODE + jj] + vj, 0.0f); \
                   sum += e; sq += e * e; mx = fmaxf(mx, e); mn = fminf(mn, e); }
            PROC(si.x); PROC(si.y); PROC(si.z); PROC(si.w);
#undef PROC
        }
        float mean = sum * (1.0f / DEG);
        float sd   = sqrtf(fmaxf(sq * (1.0f / DEG) - mean * mean, 0.0f) + 1e-5f);

        float* zr = &z_s[m * (TOW * KEFF) + t * KEFF];
        zr[o]       = h[n * NODE + jj];
        zr[32 + o]  = mean;
        zr[64 + o]  = mx;
        zr[96 + o]  = mn;
        zr[128 + o] = sd;
    }
    __syncthreads();

    // ---- Phase B: posttrans hp = relu(z @ W_eff + b_post), f32x2-packed K
    {
        u64 acc2[MB / 2];
#pragma unroll
        for (int mp = 0; mp < MB / 2; mp++) acc2[mp] = 0ull;
        const float* W = g_WeffT + t * KEFF * OUT_T + o * 4;
#pragma unroll 4
        for (int k4 = 0; k4 < KEFF / 4; k4++) {
            float4 w4 = *(const float4*)&W[k4 * (OUT_T * 4)];
            u64 w01, w23;
            PACK2(w01, w4.x, w4.y);
            PACK2(w23, w4.z, w4.w);
#pragma unroll
            for (int mp = 0; mp < MB / 2; mp++) {
                int m = mp * 2 + half;
                ulonglong2 z2 = *(const ulonglong2*)&z_s[m * (TOW * KEFF) + t * KEFF + k4 * 4];
                FMA2(acc2[mp], z2.x, w01, acc2[mp]);
                FMA2(acc2[mp], z2.y, w23, acc2[mp]);
            }
        }
        float bp = b_post[t * OUT_T + o];
#pragma unroll
        for (int mp = 0; mp < MB / 2; mp++) {
            int m = mp * 2 + half;
            hp_s[m * NODE + jj] = fmaxf(bp + hsum2(acc2[mp]), 0.0f);
        }
    }
    __syncthreads();

    // ---- Phase C: mix leaky_relu(hp @ W_mix + b_mix) + residual, packed K
    {
        u64 acc2[MB / 2];
#pragma unroll
        for (int mp = 0; mp < MB / 2; mp++) acc2[mp] = 0ull;
        const float* Wm = g_WmixT + jj * 4;
#pragma unroll 4
        for (int k4 = 0; k4 < NODE / 4; k4++) {
            float4 w4 = *(const float4*)&Wm[k4 * (NODE * 4)];
            u64 w01, w23;
            PACK2(w01, w4.x, w4.y);
            PACK2(w23, w4.z, w4.w);
#pragma unroll
            for (int mp = 0; mp < MB / 2; mp++) {
                int m = mp * 2 + half;
                ulonglong2 h2 = *(const ulonglong2*)&hp_s[m * NODE + k4 * 4];
                FMA2(acc2[mp], h2.x, w01, acc2[mp]);
                FMA2(acc2[mp], h2.y, w23, acc2[mp]);
            }
        }
        float bm = b_mix[jj];
#pragma unroll
        for (int mp = 0; mp < MB / 2; mp++) {
            int m = mp * 2 + half;
            int n = base + m;
            float x  = bm + hsum2(acc2[mp]);
            float lo = (x >= 0.0f) ? x : 0.01f * x;
            out[n * NODE + jj] = h[n * NODE + jj] + lo;
        }
    }
}

// ---------------------------------------------------------------------------
extern "C" void kernel_launch(void* const* d_in, const int* in_sizes, int n_in,
                              void* d_out, int out_size) {
    const float* h      = (const float*)d_in[0];
    const int*   src    = (const int*)  d_in[1];
    // d_in[2] = dst (repeat(arange(N), DEG) -> implicit)
    const float* W_pre  = (const float*)d_in[3];
    const float* b_pre  = (const float*)d_in[4];
    const float* W_post = (const float*)d_in[5];
    const float* b_post = (const float*)d_in[6];
    const float* W_mix  = (const float*)d_in[7];
    const float* b_mix  = (const float*)d_in[8];
    float* out = (float*)d_out;

    const int NFOLD = TOW * KEFF * OUT_T + NODE * NODE;
    k_fold<<<(NFOLD + 255) / 256, 256>>>(W_post, W_mix);
    k_uv  <<<(NN + 31) / 32, 128>>>(h, W_pre, b_pre);
    k_main<<<NN / MB, 256>>>(h, src, b_post, b_mix, out);
}

// round 9
// speedup vs baseline: 1.4538x; 1.4056x over previous
#include <cuda_runtime.h>
#include <math.h>

#define NN      50000
#define DEG     32
#define NODE    128
#define TOW     4
#define IN_T    32
#define OUT_T   32
#define KEFF    160          // folded posttrans inner dim: 32 (ht) + 128 (agg)
#define MB      16           // nodes per block in main kernel

typedef unsigned long long u64;

// Scratch (device-global: no runtime allocation allowed)
__device__ float g_u[NN * NODE];                 // 25.6 MB
__device__ float g_v[NN * NODE];                 // 25.6 MB
__device__ float g_WeffT[TOW * KEFF * OUT_T];    // folded posttrans, [t][k/4][o][4]
__device__ float g_WmixT[NODE * NODE];           // W_mix, [k/4][j][4]
__device__ float g_WpreTu[TOW * IN_T * OUT_T];   // W_pre src-half, [t][k/4][o][4]
__device__ float g_WpreTv[TOW * IN_T * OUT_T];   // W_pre dst-half, [t][k/4][o][4]

// ---- packed f32x2 helpers -------------------------------------------------
#define FMA2(d, a, b, c) asm("fma.rn.f32x2 %0, %1, %2, %3;" : "=l"(d) : "l"(a), "l"(b), "l"(c))
#define PACK2(out, lo, hi) asm("mov.b64 %0, {%1, %2};" : "=l"(out) : "f"(lo), "f"(hi))
__device__ __forceinline__ float hsum2(u64 v) {
    unsigned int lo, hi;
    asm("mov.b64 {%0, %1}, %2;" : "=r"(lo), "=r"(hi) : "l"(v));
    return __uint_as_float(lo) + __uint_as_float(hi);
}

// ---------------------------------------------------------------------------
// Kernel 0: weight preprocessing.
//  - fold deg-scalers into W_post -> g_WeffT  [t][k/4][o][4]
//  - transpose W_mix -> g_WmixT               [k/4][j][4]
//  - split+transpose W_pre -> g_WpreTu/g_WpreTv [t][k/4][o][4]
// ---------------------------------------------------------------------------
__global__ void k_fold(const float* __restrict__ W_post,
                       const float* __restrict__ W_mix,
                       const float* __restrict__ W_pre) {
    int i = blockIdx.x * 256 + threadIdx.x;
    const int NW   = TOW * KEFF * OUT_T;            // 20480
    const int NMIX = NODE * NODE;                   // 16384
    const int NPRE = TOW * 64 * OUT_T;              // 8192
    if (i < NW) {
        int o = i & 31;
        int k = (i >> 5) % KEFF;
        int t = i / (KEFF * OUT_T);
        const float sc  = logf((float)(DEG + 1)) / logf(5.0f);
        const float isc = 1.0f / sc;
        const float* Wt = W_post + t * 416 * OUT_T;
        float w;
        if (k < 32) {
            w = Wt[k * OUT_T + o];
        } else {
            int ka = k - 32;
            w = Wt[(32 + ka) * OUT_T + o]
              + sc  * Wt[(160 + ka) * OUT_T + o]
              + isc * Wt[(288 + ka) * OUT_T + o];
        }
        g_WeffT[t * KEFF * OUT_T + (k >> 2) * (OUT_T * 4) + o * 4 + (k & 3)] = w;
    } else if (i < NW + NMIX) {
        int j = i - NW;
        int k = j >> 7, col = j & 127;
        g_WmixT[(k >> 2) * (NODE * 4) + col * 4 + (k & 3)] = W_mix[k * NODE + col];
    } else if (i < NW + NMIX + NPRE) {
        int j  = i - NW - NMIX;                     // over [t][kk][o], kk in [0,64)
        int o  = j & 31;
        int kk = (j >> 5) & 63;
        int t  = j >> 11;
        float w = W_pre[t * (64 * OUT_T) + kk * OUT_T + o];
        int k = kk & 31;
        int idx = t * (IN_T * OUT_T) + (k >> 2) * (OUT_T * 4) + o * 4 + (k & 3);
        if (kk < 32) g_WpreTu[idx] = w;
        else         g_WpreTv[idx] = w;
    }
}

// ---------------------------------------------------------------------------
// Kernel 1: per-node pretrans halves, register-resident packed weights.
// u = ht@Wpre[:32], v = ht@Wpre[32:]+b.  128 threads = (t,o); 32 nodes/block.
// ---------------------------------------------------------------------------
__global__ void __launch_bounds__(128) k_uv(const float* __restrict__ h,
                                            const float* __restrict__ b_pre) {
    __shared__ __align__(16) float hts[32 * NODE];   // 16 KB
    int tid  = threadIdx.x;
    int base = blockIdx.x * 32;
    int nloc = NN - base; if (nloc > 32) nloc = 32;

    {   // cooperative vectorized load of the node tile
        const float4* hs = (const float4*)(h + (size_t)base * NODE);
        float4* hd = (float4*)hts;
        for (int i = tid; i < nloc * (NODE / 4); i += 128) hd[i] = hs[i];
    }
    __syncthreads();

    int t = tid >> 5, o = tid & 31;

    // pack weights into registers once per block
    u64 wu[16], wv[16];
    const float* Wu = g_WpreTu + t * (IN_T * OUT_T) + o * 4;
    const float* Wv = g_WpreTv + t * (IN_T * OUT_T) + o * 4;
#pragma unroll
    for (int k4 = 0; k4 < 8; k4++) {
        float4 a = *(const float4*)&Wu[k4 * (OUT_T * 4)];
        PACK2(wu[2 * k4],     a.x, a.y);
        PACK2(wu[2 * k4 + 1], a.z, a.w);
        float4 b = *(const float4*)&Wv[k4 * (OUT_T * 4)];
        PACK2(wv[2 * k4],     b.x, b.y);
        PACK2(wv[2 * k4 + 1], b.z, b.w);
    }
    float bp = b_pre[t * OUT_T + o];

    for (int m = 0; m < nloc; m++) {
        const float* zr = &hts[m * NODE + t * IN_T];
        u64 au = 0ull, av = 0ull;
#pragma unroll
        for (int k4 = 0; k4 < 8; k4++) {
            ulonglong2 z2 = *(const ulonglong2*)&zr[k4 * 4];
            FMA2(au, z2.x, wu[2 * k4],     au);
            FMA2(au, z2.y, wu[2 * k4 + 1], au);
            FMA2(av, z2.x, wv[2 * k4],     av);
            FMA2(av, z2.y, wv[2 * k4 + 1], av);
        }
        int n = base + m;
        g_u[n * NODE + tid] = hsum2(au);
        g_v[n * NODE + tid] = hsum2(av) + bp;
    }
}

// ---------------------------------------------------------------------------
// Kernel 2: gather+aggregate -> posttrans (f32x2 packed) -> mix -> residual.
// Phase A: each thread owns a feature PAIR (LDG.64 gathers), warp-uniform node.
// ---------------------------------------------------------------------------
__global__ void __launch_bounds__(256) k_main(const float* __restrict__ h,
                                              const int*   __restrict__ src,
                                              const float* __restrict__ b_post,
                                              const float* __restrict__ b_mix,
                                              float*       __restrict__ out) {
    __shared__ __align__(16) float z_s[MB * TOW * KEFF];   // 40 KB
    __shared__ __align__(16) float hp_s[MB * NODE];        //  8 KB

    int tid  = threadIdx.x;
    int base = blockIdx.x * MB;

    // ---- Phase A: gather u[src] (float2), e = relu(u+v), mean/max/min/std
    {
        int p    = tid & 63;        // feature-pair index: features {2p, 2p+1}
        int slot = tid >> 6;        // node slot 0..3 (warp-uniform)
        int f0   = p * 2;
        int t    = f0 >> 5, o = f0 & 31;

        for (int mq = 0; mq < MB / 4; mq++) {
            int m = mq * 4 + slot;
            int n = base + m;
            float2 vj = *(const float2*)&g_v[n * NODE + f0];
            const int4* sp4 = (const int4*)(src + n * DEG);
            int4 s[DEG / 4];
#pragma unroll
            for (int i = 0; i < DEG / 4; i++) s[i] = sp4[i];  // warp-uniform

            float sx = 0.0f, sy = 0.0f, qx = 0.0f, qy = 0.0f;
            float mxx = -3.4e38f, mxy = -3.4e38f, mnx = 3.4e38f, mny = 3.4e38f;
#pragma unroll
            for (int i = 0; i < DEG / 4; i++) {
                int4 si = s[i];
#define PROC(SS) { float2 uu = *(const float2*)&g_u[(SS) * NODE + f0];           \
                   float ex = fmaxf(uu.x + vj.x, 0.0f);                          \
                   float ey = fmaxf(uu.y + vj.y, 0.0f);                          \
                   sx += ex; sy += ey; qx += ex * ex; qy += ey * ey;             \
                   mxx = fmaxf(mxx, ex); mxy = fmaxf(mxy, ey);                   \
                   mnx = fminf(mnx, ex); mny = fminf(mny, ey); }
                PROC(si.x); PROC(si.y); PROC(si.z); PROC(si.w);
#undef PROC
            }
            float meanx = sx * (1.0f / DEG), meany = sy * (1.0f / DEG);
            float sdx = sqrtf(fmaxf(qx * (1.0f / DEG) - meanx * meanx, 0.0f) + 1e-5f);
            float sdy = sqrtf(fmaxf(qy * (1.0f / DEG) - meany * meany, 0.0f) + 1e-5f);

            float2 h2 = *(const float2*)&h[n * NODE + f0];
            float* zr = &z_s[m * (TOW * KEFF) + t * KEFF];
            *(float2*)&zr[o]        = h2;
            *(float2*)&zr[32 + o]   = make_float2(meanx, meany);
            *(float2*)&zr[64 + o]   = make_float2(mxx, mxy);
            *(float2*)&zr[96 + o]   = make_float2(mnx, mny);
            *(float2*)&zr[128 + o]  = make_float2(sdx, sdy);
        }
    }
    __syncthreads();

    int half = tid >> 7;
    int jj   = tid & 127;
    int t    = jj >> 5, o = jj & 31;

    // ---- Phase B: posttrans hp = relu(z @ W_eff + b_post), f32x2-packed K
    {
        u64 acc2[MB / 2];
#pragma unroll
        for (int mp = 0; mp < MB / 2; mp++) acc2[mp] = 0ull;
        const float* W = g_WeffT + t * KEFF * OUT_T + o * 4;
#pragma unroll 4
        for (int k4 = 0; k4 < KEFF / 4; k4++) {
            float4 w4 = *(const float4*)&W[k4 * (OUT_T * 4)];
            u64 w01, w23;
            PACK2(w01, w4.x, w4.y);
            PACK2(w23, w4.z, w4.w);
#pragma unroll
            for (int mp = 0; mp < MB / 2; mp++) {
                int m = mp * 2 + half;
                ulonglong2 z2 = *(const ulonglong2*)&z_s[m * (TOW * KEFF) + t * KEFF + k4 * 4];
                FMA2(acc2[mp], z2.x, w01, acc2[mp]);
                FMA2(acc2[mp], z2.y, w23, acc2[mp]);
            }
        }
        float bp = b_post[t * OUT_T + o];
#pragma unroll
        for (int mp = 0; mp < MB / 2; mp++) {
            int m = mp * 2 + half;
            hp_s[m * NODE + jj] = fmaxf(bp + hsum2(acc2[mp]), 0.0f);
        }
    }
    __syncthreads();

    // ---- Phase C: mix leaky_relu(hp @ W_mix + b_mix) + residual, packed K
    {
        u64 acc2[MB / 2];
#pragma unroll
        for (int mp = 0; mp < MB / 2; mp++) acc2[mp] = 0ull;
        const float* Wm = g_WmixT + jj * 4;
#pragma unroll 4
        for (int k4 = 0; k4 < NODE / 4; k4++) {
            float4 w4 = *(const float4*)&Wm[k4 * (NODE * 4)];
            u64 w01, w23;
            PACK2(w01, w4.x, w4.y);
            PACK2(w23, w4.z, w4.w);
#pragma unroll
            for (int mp = 0; mp < MB / 2; mp++) {
                int m = mp * 2 + half;
                ulonglong2 h2 = *(const ulonglong2*)&hp_s[m * NODE + k4 * 4];
                FMA2(acc2[mp], h2.x, w01, acc2[mp]);
                FMA2(acc2[mp], h2.y, w23, acc2[mp]);
            }
        }
        float bm = b_mix[jj];
#pragma unroll
        for (int mp = 0; mp < MB / 2; mp++) {
            int m = mp * 2 + half;
            int n = base + m;
            float x  = bm + hsum2(acc2[mp]);
            float lo = (x >= 0.0f) ? x : 0.01f * x;
            out[n * NODE + jj] = h[n * NODE + jj] + lo;
        }
    }
}

// ---------------------------------------------------------------------------
extern "C" void kernel_launch(void* const* d_in, const int* in_sizes, int n_in,
                              void* d_out, int out_size) {
    const float* h      = (const float*)d_in[0];
    const int*   src    = (const int*)  d_in[1];
    // d_in[2] = dst (repeat(arange(N), DEG) -> implicit)
    const float* W_pre  = (const float*)d_in[3];
    const float* b_pre  = (const float*)d_in[4];
    const float* W_post = (const float*)d_in[5];
    const float* b_post = (const float*)d_in[6];
    const float* W_mix  = (const float*)d_in[7];
    const float* b_mix  = (const float*)d_in[8];
    float* out = (float*)d_out;

    const int NFOLD = TOW * KEFF * OUT_T + NODE * NODE + TOW * 64 * OUT_T;
    k_fold<<<(NFOLD + 255) / 256, 256>>>(W_post, W_mix, W_pre);
    k_uv  <<<(NN + 31) / 32, 128>>>(h, b_pre);
    k_main<<<NN / MB, 256>>>(h, src, b_post, b_mix, out);
}

// round 14
// speedup vs baseline: 1.5060x; 1.0359x over previous
#include <cuda_runtime.h>
#include <math.h>

#define NN      50000
#define DEG     32
#define NODE    128
#define TOW     4
#define IN_T    32
#define OUT_T   32
#define KEFF    160          // folded posttrans inner dim: 32 (ht) + 128 (agg)
#define MB      16           // nodes per block in main kernel

typedef unsigned long long u64;

// Scratch (device-global: no runtime allocation allowed)
__device__ float g_u[NN * NODE];                 // 25.6 MB
__device__ float g_v[NN * NODE];                 // 25.6 MB
__device__ float g_WeffT[TOW * KEFF * OUT_T];    // folded posttrans, [t][k/4][o][4]
__device__ float g_WmixT[NODE * NODE];           // W_mix, [k/4][j][4]
__device__ float g_WpreTu[TOW * IN_T * OUT_T];   // W_pre src-half, [t][k/4][o][4]
__device__ float g_WpreTv[TOW * IN_T * OUT_T];   // W_pre dst-half, [t][k/4][o][4]

// ---- packed f32x2 helpers -------------------------------------------------
#define FMA2(d, a, b, c) asm("fma.rn.f32x2 %0, %1, %2, %3;" : "=l"(d) : "l"(a), "l"(b), "l"(c))
#define PACK2(out, lo, hi) asm("mov.b64 %0, {%1, %2};" : "=l"(out) : "f"(lo), "f"(hi))
__device__ __forceinline__ float hsum2(u64 v) {
    unsigned int lo, hi;
    asm("mov.b64 {%0, %1}, %2;" : "=r"(lo), "=r"(hi) : "l"(v));
    return __uint_as_float(lo) + __uint_as_float(hi);
}

// ---------------------------------------------------------------------------
// Kernel 0: weight preprocessing.
// ---------------------------------------------------------------------------
__global__ void k_fold(const float* __restrict__ W_post,
                       const float* __restrict__ W_mix,
                       const float* __restrict__ W_pre) {
    int i = blockIdx.x * 256 + threadIdx.x;
    const int NW   = TOW * KEFF * OUT_T;            // 20480
    const int NMIX = NODE * NODE;                   // 16384
    const int NPRE = TOW * 64 * OUT_T;              // 8192
    if (i < NW) {
        int o = i & 31;
        int k = (i >> 5) % KEFF;
        int t = i / (KEFF * OUT_T);
        const float sc  = logf((float)(DEG + 1)) / logf(5.0f);
        const float isc = 1.0f / sc;
        const float* Wt = W_post + t * 416 * OUT_T;
        float w;
        if (k < 32) {
            w = Wt[k * OUT_T + o];
        } else {
            int ka = k - 32;
            w = Wt[(32 + ka) * OUT_T + o]
              + sc  * Wt[(160 + ka) * OUT_T + o]
              + isc * Wt[(288 + ka) * OUT_T + o];
        }
        g_WeffT[t * KEFF * OUT_T + (k >> 2) * (OUT_T * 4) + o * 4 + (k & 3)] = w;
    } else if (i < NW + NMIX) {
        int j = i - NW;
        int k = j >> 7, col = j & 127;
        g_WmixT[(k >> 2) * (NODE * 4) + col * 4 + (k & 3)] = W_mix[k * NODE + col];
    } else if (i < NW + NMIX + NPRE) {
        int j  = i - NW - NMIX;
        int o  = j & 31;
        int kk = (j >> 5) & 63;
        int t  = j >> 11;
        float w = W_pre[t * (64 * OUT_T) + kk * OUT_T + o];
        int k = kk & 31;
        int idx = t * (IN_T * OUT_T) + (k >> 2) * (OUT_T * 4) + o * 4 + (k & 3);
        if (kk < 32) g_WpreTu[idx] = w;
        else         g_WpreTv[idx] = w;
    }
}

// ---------------------------------------------------------------------------
// Kernel 1: per-node pretrans halves, register-resident packed weights.
// ---------------------------------------------------------------------------
__global__ void __launch_bounds__(128) k_uv(const float* __restrict__ h,
                                            const float* __restrict__ b_pre) {
    __shared__ __align__(16) float hts[32 * NODE];   // 16 KB
    int tid  = threadIdx.x;
    int base = blockIdx.x * 32;
    int nloc = NN - base; if (nloc > 32) nloc = 32;

    {
        const float4* hs = (const float4*)(h + (size_t)base * NODE);
        float4* hd = (float4*)hts;
        for (int i = tid; i < nloc * (NODE / 4); i += 128) hd[i] = hs[i];
    }
    __syncthreads();

    int t = tid >> 5, o = tid & 31;

    u64 wu[16], wv[16];
    const float* Wu = g_WpreTu + t * (IN_T * OUT_T) + o * 4;
    const float* Wv = g_WpreTv + t * (IN_T * OUT_T) + o * 4;
#pragma unroll
    for (int k4 = 0; k4 < 8; k4++) {
        float4 a = *(const float4*)&Wu[k4 * (OUT_T * 4)];
        PACK2(wu[2 * k4],     a.x, a.y);
        PACK2(wu[2 * k4 + 1], a.z, a.w);
        float4 b = *(const float4*)&Wv[k4 * (OUT_T * 4)];
        PACK2(wv[2 * k4],     b.x, b.y);
        PACK2(wv[2 * k4 + 1], b.z, b.w);
    }
    float bp = b_pre[t * OUT_T + o];

    for (int m = 0; m < nloc; m++) {
        const float* zr = &hts[m * NODE + t * IN_T];
        u64 au = 0ull, av = 0ull;
#pragma unroll
        for (int k4 = 0; k4 < 8; k4++) {
            ulonglong2 z2 = *(const ulonglong2*)&zr[k4 * 4];
            FMA2(au, z2.x, wu[2 * k4],     au);
            FMA2(au, z2.y, wu[2 * k4 + 1], au);
            FMA2(av, z2.x, wv[2 * k4],     av);
            FMA2(av, z2.y, wv[2 * k4 + 1], av);
        }
        int n = base + m;
        g_u[n * NODE + tid] = hsum2(au);
        g_v[n * NODE + tid] = hsum2(av) + bp;
    }
}

// ---------------------------------------------------------------------------
// Kernel 2: gather+aggregate -> posttrans -> mix -> residual.
// Phase A: one WARP per node, each lane owns a feature QUAD -> every gather is
// a single warp-wide LDG.128 covering a full 512B u-row (max MLP, min LSU).
// ---------------------------------------------------------------------------
__global__ void __launch_bounds__(256) k_main(const float* __restrict__ h,
                                              const int*   __restrict__ src,
                                              const float* __restrict__ b_post,
                                              const float* __restrict__ b_mix,
                                              float*       __restrict__ out) {
    __shared__ __align__(16) float z_s[MB * TOW * KEFF];   // 40 KB
    __shared__ __align__(16) float hp_s[MB * NODE];        //  8 KB

    int tid  = threadIdx.x;
    int base = blockIdx.x * MB;

    // ---- Phase A: gather u[src] (float4/row), e = relu(u+v), mean/max/min/std
    {
        int lane = tid & 31;          // feature quad: features 4*lane..4*lane+3
        int w    = tid >> 5;          // warp id 0..7 -> node owner
        int f0   = lane * 4;
        int t    = f0 >> 5, o = f0 & 31;

        for (int it = 0; it < MB / 8; it++) {
            int m = it * 8 + w;
            int n = base + m;
            float4 vj = *(const float4*)&g_v[n * NODE + f0];
            const int4* sp4 = (const int4*)(src + n * DEG);
            int4 s[DEG / 4];
#pragma unroll
            for (int i = 0; i < DEG / 4; i++) s[i] = sp4[i];   // warp-uniform

            float4 sum = make_float4(0.f, 0.f, 0.f, 0.f);
            float4 sq  = make_float4(0.f, 0.f, 0.f, 0.f);
            float4 mx  = make_float4(-3.4e38f, -3.4e38f, -3.4e38f, -3.4e38f);
            float4 mn  = make_float4(3.4e38f, 3.4e38f, 3.4e38f, 3.4e38f);
#pragma unroll
            for (int i = 0; i < DEG / 4; i++) {
                int4 si = s[i];
#define PROC(SS) { float4 uu = *(const float4*)&g_u[(SS) * NODE + f0];            \
                   float ex = fmaxf(uu.x + vj.x, 0.f), ey = fmaxf(uu.y + vj.y, 0.f); \
                   float ez = fmaxf(uu.z + vj.z, 0.f), ew = fmaxf(uu.w + vj.w, 0.f); \
                   sum.x += ex; sum.y += ey; sum.z += ez; sum.w += ew;            \
                   sq.x += ex*ex; sq.y += ey*ey; sq.z += ez*ez; sq.w += ew*ew;    \
                   mx.x = fmaxf(mx.x, ex); mx.y = fmaxf(mx.y, ey);                \
                   mx.z = fmaxf(mx.z, ez); mx.w = fmaxf(mx.w, ew);                \
                   mn.x = fminf(mn.x, ex); mn.y = fminf(mn.y, ey);                \
                   mn.z = fminf(mn.z, ez); mn.w = fminf(mn.w, ew); }
                PROC(si.x); PROC(si.y); PROC(si.z); PROC(si.w);
#undef PROC
            }
            const float id = 1.0f / DEG;
            float4 mean = make_float4(sum.x * id, sum.y * id, sum.z * id, sum.w * id);
            float4 sd;
            sd.x = sqrtf(fmaxf(sq.x * id - mean.x * mean.x, 0.f) + 1e-5f);
            sd.y = sqrtf(fmaxf(sq.y * id - mean.y * mean.y, 0.f) + 1e-5f);
            sd.z = sqrtf(fmaxf(sq.z * id - mean.z * mean.z, 0.f) + 1e-5f);
            sd.w = sqrtf(fmaxf(sq.w * id - mean.w * mean.w, 0.f) + 1e-5f);

            float4 h4 = *(const float4*)&h[n * NODE + f0];
            float* zr = &z_s[m * (TOW * KEFF) + t * KEFF];
            *(float4*)&zr[o]        = h4;
            *(float4*)&zr[32 + o]   = mean;
            *(float4*)&zr[64 + o]   = mx;
            *(float4*)&zr[96 + o]   = mn;
            *(float4*)&zr[128 + o]  = sd;
        }
    }
    __syncthreads();

    int half = tid >> 7;
    int jj   = tid & 127;
    int t    = jj >> 5, o = jj & 31;

    // ---- Phase B: posttrans hp = relu(z @ W_eff + b_post), f32x2-packed K
    {
        u64 acc2[MB / 2];
#pragma unroll
        for (int mp = 0; mp < MB / 2; mp++) acc2[mp] = 0ull;
        const float* W = g_WeffT + t * KEFF * OUT_T + o * 4;
#pragma unroll 4
        for (int k4 = 0; k4 < KEFF / 4; k4++) {
            float4 w4 = *(const float4*)&W[k4 * (OUT_T * 4)];
            u64 w01, w23;
            PACK2(w01, w4.x, w4.y);
            PACK2(w23, w4.z, w4.w);
#pragma unroll
            for (int mp = 0; mp < MB / 2; mp++) {
                int m = mp * 2 + half;
                ulonglong2 z2 = *(const ulonglong2*)&z_s[m * (TOW * KEFF) + t * KEFF + k4 * 4];
                FMA2(acc2[mp], z2.x, w01, acc2[mp]);
                FMA2(acc2[mp], z2.y, w23, acc2[mp]);
            }
        }
        float bp = b_post[t * OUT_T + o];
#pragma unroll
        for (int mp = 0; mp < MB / 2; mp++) {
            int m = mp * 2 + half;
            hp_s[m * NODE + jj] = fmaxf(bp + hsum2(acc2[mp]), 0.0f);
        }
    }
    __syncthreads();

    // ---- Phase C: mix leaky_relu(hp @ W_mix + b_mix) + residual, packed K
    {
        u64 acc2[MB / 2];
#pragma unroll
        for (int mp = 0; mp < MB / 2; mp++) acc2[mp] = 0ull;
        const float* Wm = g_WmixT + jj * 4;
#pragma unroll 4
        for (int k4 = 0; k4 < NODE / 4; k4++) {
            float4 w4 = *(const float4*)&Wm[k4 * (NODE * 4)];
            u64 w01, w23;
            PACK2(w01, w4.x, w4.y);
            PACK2(w23, w4.z, w4.w);
#pragma unroll
            for (int mp = 0; mp < MB / 2; mp++) {
                int m = mp * 2 + half;
                ulonglong2 h2 = *(const ulonglong2*)&hp_s[m * NODE + k4 * 4];
                FMA2(acc2[mp], h2.x, w01, acc2[mp]);
                FMA2(acc2[mp], h2.y, w23, acc2[mp]);
            }
        }
        float bm = b_mix[jj];
#pragma unroll
        for (int mp = 0; mp < MB / 2; mp++) {
            int m = mp * 2 + half;
            int n = base + m;
            float x  = bm + hsum2(acc2[mp]);
            float lo = (x >= 0.0f) ? x : 0.01f * x;
            out[n * NODE + jj] = h[n * NODE + jj] + lo;
        }
    }
}

// ---------------------------------------------------------------------------
extern "C" void kernel_launch(void* const* d_in, const int* in_sizes, int n_in,
                              void* d_out, int out_size) {
    const float* h      = (const float*)d_in[0];
    const int*   src    = (const int*)  d_in[1];
    // d_in[2] = dst (repeat(arange(N), DEG) -> implicit)
    const float* W_pre  = (const float*)d_in[3];
    const float* b_pre  = (const float*)d_in[4];
    const float* W_post = (const float*)d_in[5];
    const float* b_post = (const float*)d_in[6];
    const float* W_mix  = (const float*)d_in[7];
    const float* b_mix  = (const float*)d_in[8];
    float* out = (float*)d_out;

    const int NFOLD = TOW * KEFF * OUT_T + NODE * NODE + TOW * 64 * OUT_T;
    k_fold<<<(NFOLD + 255) / 256, 256>>>(W_post, W_mix, W_pre);
    k_uv  <<<(NN + 31) / 32, 128>>>(h, b_pre);
    k_main<<<NN / MB, 256>>>(h, src, b_post, b_mix, out);
}